// round 14
// baseline (speedup 1.0000x reference)
#include <cuda_runtime.h>
#include <cuda_fp16.h>
#include <cstdint>

#define NN 64
#define CC 256
#define TT 64
#define VV 25
#define VP2 26
#define TVP (TT * VP2)            // 1664 padded cols = 13 x 128
#define NROWS (NN * CC * TT)
#define ELEMS26 (NROWS * VP2)

typedef unsigned long long ull;

// Device scratch (no cudaMalloc allowed)
__device__ float g_r0[ELEMS26];                  // residual ping (padded 26)
__device__ float g_r1[ELEMS26];                  // residual pong (padded 26)
__device__ __half g_yh[ELEMS26];                 // mixed, fp16 (padded 26)
__device__ __half g_whi[4 * CC * CC];            // W fp16 hi
__device__ __half g_wlo[4 * CC * CC];            // W fp16 lo

// ---------------- PTX helpers ----------------
__device__ __forceinline__ uint32_t smem_u32(const void* p) {
    uint32_t a;
    asm("{ .reg .u64 t; cvta.to.shared.u64 t, %1; cvt.u32.u64 %0, t; }" : "=r"(a) : "l"(p));
    return a;
}
__device__ __forceinline__ ull ffma2(ull a, ull b, ull c) {
    ull d; asm("fma.rn.f32x2 %0, %1, %2, %3;" : "=l"(d) : "l"(a), "l"(b), "l"(c)); return d;
}
__device__ __forceinline__ ull pack2(float x) {
    ull d; unsigned xu = __float_as_uint(x);
    asm("mov.b64 %0, {%1, %2};" : "=l"(d) : "r"(xu), "r"(xu)); return d;
}
__device__ __forceinline__ ull pack2f(float lo, float hi) {
    ull d; asm("mov.b64 %0, {%1, %2};" : "=l"(d) : "r"(__float_as_uint(lo)), "r"(__float_as_uint(hi))); return d;
}
__device__ __forceinline__ float lo32(ull a) { return __uint_as_float((unsigned)(a & 0xffffffffULL)); }
__device__ __forceinline__ float hi32(ull a) { return __uint_as_float((unsigned)(a >> 32)); }

__device__ __forceinline__ void ldsm_x4(uint32_t* r, uint32_t addr) {
    asm volatile("ldmatrix.sync.aligned.m8n8.x4.shared.b16 {%0,%1,%2,%3}, [%4];"
                 : "=r"(r[0]), "=r"(r[1]), "=r"(r[2]), "=r"(r[3]) : "r"(addr));
}
__device__ __forceinline__ void ldsm_x4_t(uint32_t* r, uint32_t addr) {
    asm volatile("ldmatrix.sync.aligned.m8n8.x4.trans.shared.b16 {%0,%1,%2,%3}, [%4];"
                 : "=r"(r[0]), "=r"(r[1]), "=r"(r[2]), "=r"(r[3]) : "r"(addr));
}
__device__ __forceinline__ void mma_f16(float* c, const uint32_t* a, const uint32_t* b) {
    asm volatile("mma.sync.aligned.m16n8k16.row.col.f32.f16.f16.f32 "
                 "{%0,%1,%2,%3}, {%4,%5,%6,%7}, {%8,%9}, {%0,%1,%2,%3};"
                 : "+f"(c[0]), "+f"(c[1]), "+f"(c[2]), "+f"(c[3])
                 : "r"(a[0]), "r"(a[1]), "r"(a[2]), "r"(a[3]), "r"(b[0]), "r"(b[1]));
}
__device__ __forceinline__ void cp16(uint32_t dst, const void* src) {
    asm volatile("cp.async.cg.shared.global [%0], [%1], 16;" :: "r"(dst), "l"(src) : "memory");
}
#define CP_COMMIT() asm volatile("cp.async.commit_group;" ::: "memory")

// ---------------- W split kernel (once, all 4 layers) ----------------
__global__ void __launch_bounds__(256)
wsplit_kernel(const float* __restrict__ w0, const float* __restrict__ w1,
              const float* __restrict__ w2, const float* __restrict__ w3,
              __half* __restrict__ whi, __half* __restrict__ wlo)
{
    int id = blockIdx.x * 256 + threadIdx.x;
    const float* ws[4] = { w0, w1, w2, w3 };
    float v = ws[id >> 16][id & 65535];
    __half h = __float2half_rn(v);
    whi[id] = h;
    wlo[id] = __float2half_rn(v - __half2float(h));
}

// ---------------- Mix: y = A-mix(res), emit fp16 padded-26 ----------------
// sin==26: direct per-row gmem reads (rows are 104B contiguous, 8B aligned)
// sin==25: slab staging (layer 0 only)
__global__ void __launch_bounds__(256)
mix_kernel(const float* __restrict__ in, const float* __restrict__ Amat,
           __half* __restrict__ yh, int sin)
{
    __shared__ __align__(16) float sbuf[6400];     // slab (sin25) / half2 out (13312B)
    __shared__ ull sAp[325];
    const int tid = threadIdx.x;
    const int blk = blockIdx.x;

    for (int i = tid; i < 325; i += 256) {
        int u = i / 13, j = i - u * 13;
        float lo = Amat[(2 * j) * VV + u];
        float hi = (2 * j + 1 < VV) ? Amat[(2 * j + 1) * VV + u] : 0.f;
        sAp[i] = pack2f(lo, hi);
    }

    float xr[VV + 1];
    if (sin == VP2) {
        // direct row read: 13 x LDG.64
        const float2* src = (const float2*)(in + (size_t)blk * (256 * VP2) + tid * VP2);
#pragma unroll
        for (int j = 0; j < 13; j++) {
            float2 v = src[j];
            xr[2 * j] = v.x; xr[2 * j + 1] = v.y;
        }
        __syncthreads();   // sAp ready
    } else {
        // slab staging for dense-25 input
        const float4* src = (const float4*)(in + (size_t)blk * (256 * 25));
        float4* dst = (float4*)sbuf;
        for (int i = tid; i < 1600; i += 256) dst[i] = src[i];
        __syncthreads();
        const int rb = tid * 25;
#pragma unroll
        for (int u = 0; u < VV; u++) xr[u] = sbuf[rb + u];
        __syncthreads();   // reads done before sbuf reuse
    }

    ull acc[13];
#pragma unroll
    for (int j = 0; j < 13; j++) acc[j] = 0ULL;
#pragma unroll
    for (int u = 0; u < VV; u++) {
        ull xu2 = pack2(xr[u]);
#pragma unroll
        for (int j = 0; j < 13; j++) acc[j] = ffma2(sAp[u * 13 + j], xu2, acc[j]);
    }

    // convert in registers, store 13 x STS.32 (13 coprime 32 => conflict-free)
    {
        uint32_t* so = (uint32_t*)sbuf + tid * 13;
#pragma unroll
        for (int j = 0; j < 13; j++) {
            __half2 h = __floats2half2_rn(lo32(acc[j]), hi32(acc[j]));
            so[j] = *(uint32_t*)&h;     // j==12 hi == 0 via A pad row
        }
    }
    __syncthreads();

    // emit: 832 x (LDS.128 + STG.128), fully coalesced
    {
        uint4* yh128 = (uint4*)((uint32_t*)yh + (size_t)blk * 3328);
        const uint4* s128 = (const uint4*)sbuf;
        for (int i = tid; i < 832; i += 256) yh128[i] = s128[i];
    }
}

// ---------------- GEMM: out = relu((Wh+Wl) @ Yh + b + res), fp16 mma.sync ----------------
// grid (13, 2, 64). 3-stage cp.async pipeline, ONE barrier per k-chunk.
// MODE: 0 = res dense25 -> out padded26 (layer 0)
//       1 = padded26 -> padded26         (layers 1,2)
//       2 = padded26 -> out dense25      (layer 3)
#define WS_STRIDE 80
#define YS_STRIDE 272
#define SM_WH 0
#define SM_WL 10240
#define SM_YH 20480
#define STAGE_BYTES 29184
#define NSTAGE 3
#define SM_TOTAL (NSTAGE * STAGE_BYTES)   // 87,552

template <int MODE>
__global__ void __launch_bounds__(256, 2)
gemm_kernel(const __half* __restrict__ yh,
            const __half* __restrict__ whi, const __half* __restrict__ wlo,
            const float* __restrict__ bias, const float* __restrict__ res,
            float* __restrict__ out)
{
    extern __shared__ __align__(16) unsigned char smem[];
    const uint32_t smu = smem_u32(smem);

    const int tid  = threadIdx.x;
    const int lane = tid & 31, wid = tid >> 5;
    const int wm   = wid >> 1, wn = wid & 1;       // 4 (M) x 2 (N)
    const int ct   = blockIdx.x;
    const int mt   = blockIdx.y;
    const int n    = blockIdx.z;
    const int col0 = ct * 128;

    const __half* Wh = whi + (size_t)(mt * 128) * CC;
    const __half* Wl = wlo + (size_t)(mt * 128) * CC;
    const __half* Yh = yh  + (size_t)n * CC * TVP + col0;

    auto issue = [&](int kc) {
        const int c0 = kc * 32;
        const uint32_t sbase = smu + (kc % NSTAGE) * STAGE_BYTES;
#pragma unroll
        for (int r = 0; r < 2; r++) {
            const int q = tid + r * 256;
            const int o = q >> 2, p = q & 3;
            const size_t wsrc = (size_t)o * CC + c0 + p * 8;
            const uint32_t wdst = sbase + o * WS_STRIDE + p * 16;
            cp16(wdst + SM_WH, Wh + wsrc);
            cp16(wdst + SM_WL, Wl + wsrc);
            const int c = q >> 4, jp = q & 15;
            const size_t ysrc = (size_t)(c0 + c) * TVP + jp * 8;
            cp16(sbase + SM_YH + c * YS_STRIDE + jp * 16, Yh + ysrc);
        }
    };

    float acc[2][8][4];
#pragma unroll
    for (int fm = 0; fm < 2; fm++)
#pragma unroll
        for (int nb = 0; nb < 8; nb++)
#pragma unroll
            for (int q = 0; q < 4; q++) acc[fm][nb][q] = 0.f;

    issue(0); CP_COMMIT();
    issue(1); CP_COMMIT();

    for (int kc = 0; kc < 8; kc++) {
        if (kc + 1 < 8) {
            asm volatile("cp.async.wait_group 1;" ::: "memory");
        } else {
            asm volatile("cp.async.wait_group 0;" ::: "memory");
        }
        __syncthreads();

        if (kc + 2 < 8) {
            issue(kc + 2);
            CP_COMMIT();
        }

        const uint32_t st  = smu + (kc % NSTAGE) * STAGE_BYTES;
        const uint32_t swh = st + SM_WH;
        const uint32_t swl = st + SM_WL;
        const uint32_t syh = st + SM_YH;

#pragma unroll
        for (int s = 0; s < 2; s++) {
            uint32_t Ah[2][4], Al[2][4];
            const uint32_t aoff = (uint32_t)(lane & 15) * WS_STRIDE + s * 32 + (lane >> 4) * 16;
            ldsm_x4(Ah[0], swh + (wm * 32 +  0) * WS_STRIDE + aoff);
            ldsm_x4(Ah[1], swh + (wm * 32 + 16) * WS_STRIDE + aoff);
            ldsm_x4(Al[0], swl + (wm * 32 +  0) * WS_STRIDE + aoff);
            ldsm_x4(Al[1], swl + (wm * 32 + 16) * WS_STRIDE + aoff);

            const uint32_t boff = (uint32_t)(s * 16 + (lane & 15)) * YS_STRIDE + (lane >> 4) * 16;
#pragma unroll
            for (int nbp = 0; nbp < 4; nbp++) {
                uint32_t Bh[4];
                const uint32_t bcol = (uint32_t)(wn * 64 + nbp * 16) * 2;
                ldsm_x4_t(Bh, syh + boff + bcol);
#pragma unroll
                for (int h = 0; h < 2; h++) {
                    const int nb = nbp * 2 + h;
                    mma_f16(acc[0][nb], Ah[0], &Bh[2 * h]);
                    mma_f16(acc[0][nb], Al[0], &Bh[2 * h]);
                    mma_f16(acc[1][nb], Ah[1], &Bh[2 * h]);
                    mma_f16(acc[1][nb], Al[1], &Bh[2 * h]);
                }
            }
        }
    }

    // ---- epilogue: relu(acc + b[o] + res) ----
    const int g = lane >> 2, tig = lane & 3;

#pragma unroll
    for (int fm = 0; fm < 2; fm++) {
        const int o0 = mt * 128 + wm * 32 + fm * 16 + g;
#pragma unroll
        for (int half = 0; half < 2; half++) {
            const int orow = o0 + half * 8;
            const float bs = bias[orow];
            const size_t rowb = (size_t)n * CC + orow;
#pragma unroll
            for (int nb = 0; nb < 8; nb++) {
                const int j = col0 + wn * 64 + nb * 8 + 2 * tig;
                const float a0 = acc[fm][nb][2 * half];
                const float a1 = acc[fm][nb][2 * half + 1];

                float r0v, r1v;
                if (MODE == 0) {
                    const int t0 = j / VP2, v0 = j - t0 * VP2;
                    const float* rp = res + ((rowb * TT + t0) * VV + v0);
                    r0v = (v0 < VV) ? rp[0] : 0.f;
                    r1v = (v0 + 1 < VV) ? rp[1] : 0.f;
                } else {
                    float2 rr = *(const float2*)(res + rowb * TVP + j);
                    r0v = rr.x; r1v = rr.y;
                }
                const float o0v = fmaxf(a0 + bs + r0v, 0.f);
                const float o1v = fmaxf(a1 + bs + r1v, 0.f);
                if (MODE == 2) {
                    const int t0 = j / VP2, v0 = j - t0 * VP2;
                    float* po = out + ((rowb * TT + t0) * VV + v0);
                    if (v0 < VV) po[0] = o0v;
                    if (v0 + 1 < VV) po[1] = o1v;
                } else {
                    *(float2*)(out + rowb * TVP + j) = make_float2(o0v, o1v);
                }
            }
        }
    }
}

// ---------------- launch ----------------
extern "C" void kernel_launch(void* const* d_in, const int* in_sizes, int n_in,
                              void* d_out, int out_size)
{
    // metadata order: t, x, A, w1, b1, w2, b2, w3, b3, w4, b4
    const float* x  = (const float*)d_in[1];
    const float* A  = (const float*)d_in[2];
    const float* W[4] = { (const float*)d_in[3], (const float*)d_in[5],
                          (const float*)d_in[7], (const float*)d_in[9] };
    const float* B[4] = { (const float*)d_in[4], (const float*)d_in[6],
                          (const float*)d_in[8], (const float*)d_in[10] };
    float* out = (float*)d_out;

    float *r0, *r1;
    __half *yh, *whi, *wlo;
    cudaGetSymbolAddress((void**)&r0,  g_r0);
    cudaGetSymbolAddress((void**)&r1,  g_r1);
    cudaGetSymbolAddress((void**)&yh,  g_yh);
    cudaGetSymbolAddress((void**)&whi, g_whi);
    cudaGetSymbolAddress((void**)&wlo, g_wlo);

    cudaFuncSetAttribute(gemm_kernel<0>,
                         cudaFuncAttributeMaxDynamicSharedMemorySize, SM_TOTAL);
    cudaFuncSetAttribute(gemm_kernel<1>,
                         cudaFuncAttributeMaxDynamicSharedMemorySize, SM_TOTAL);
    cudaFuncSetAttribute(gemm_kernel<2>,
                         cudaFuncAttributeMaxDynamicSharedMemorySize, SM_TOTAL);

    wsplit_kernel<<<1024, 256>>>(W[0], W[1], W[2], W[3], whi, wlo);

    dim3 ggrid(13, 2, NN);

    // layer 0: res = x (dense 25), out = r0 (padded)
    mix_kernel<<<NROWS / 256, 256>>>(x, A, yh, 25);
    gemm_kernel<0><<<ggrid, 256, SM_TOTAL>>>(yh, whi + 0 * CC * CC,
                                             wlo + 0 * CC * CC, B[0], x, r0);
    // layer 1: padded -> padded (r0 -> r1)
    mix_kernel<<<NROWS / 256, 256>>>(r0, A, yh, 26);
    gemm_kernel<1><<<ggrid, 256, SM_TOTAL>>>(yh, whi + 1 * CC * CC,
                                             wlo + 1 * CC * CC, B[1], r0, r1);
    // layer 2: padded -> padded (r1 -> r0)
    mix_kernel<<<NROWS / 256, 256>>>(r1, A, yh, 26);
    gemm_kernel<1><<<ggrid, 256, SM_TOTAL>>>(yh, whi + 2 * CC * CC,
                                             wlo + 2 * CC * CC, B[2], r1, r0);
    // layer 3: padded -> dense out
    mix_kernel<<<NROWS / 256, 256>>>(r0, A, yh, 26);
    gemm_kernel<2><<<ggrid, 256, SM_TOTAL>>>(yh, whi + 3 * CC * CC,
                                             wlo + 3 * CC * CC, B[3], r0, out);
}

// round 15
// speedup vs baseline: 1.1743x; 1.1743x over previous
#include <cuda_runtime.h>
#include <cuda_fp16.h>
#include <cstdint>

#define NN 64
#define CC 256
#define TT 64
#define VV 25
#define VP2 26
#define TVP (TT * VP2)            // 1664 padded cols = 13 x 128
#define NROWS (NN * CC * TT)
#define ELEMS26 (NROWS * VP2)

typedef unsigned long long ull;

// Device scratch (no cudaMalloc allowed)
__device__ float g_r0[ELEMS26];                  // residual ping (padded 26)
__device__ float g_r1[ELEMS26];                  // residual pong (padded 26)
__device__ __half g_yh[ELEMS26];                 // mixed, fp16 (padded 26)
__device__ __half g_wh[4 * CC * CC];             // W fp16 (rounded)

// ---------------- PTX helpers ----------------
__device__ __forceinline__ uint32_t smem_u32(const void* p) {
    uint32_t a;
    asm("{ .reg .u64 t; cvta.to.shared.u64 t, %1; cvt.u32.u64 %0, t; }" : "=r"(a) : "l"(p));
    return a;
}
__device__ __forceinline__ ull ffma2(ull a, ull b, ull c) {
    ull d; asm("fma.rn.f32x2 %0, %1, %2, %3;" : "=l"(d) : "l"(a), "l"(b), "l"(c)); return d;
}
__device__ __forceinline__ ull pack2(float x) {
    ull d; unsigned xu = __float_as_uint(x);
    asm("mov.b64 %0, {%1, %2};" : "=l"(d) : "r"(xu), "r"(xu)); return d;
}
__device__ __forceinline__ ull pack2f(float lo, float hi) {
    ull d; asm("mov.b64 %0, {%1, %2};" : "=l"(d) : "r"(__float_as_uint(lo)), "r"(__float_as_uint(hi))); return d;
}
__device__ __forceinline__ float lo32(ull a) { return __uint_as_float((unsigned)(a & 0xffffffffULL)); }
__device__ __forceinline__ float hi32(ull a) { return __uint_as_float((unsigned)(a >> 32)); }

__device__ __forceinline__ void ldsm_x4(uint32_t* r, uint32_t addr) {
    asm volatile("ldmatrix.sync.aligned.m8n8.x4.shared.b16 {%0,%1,%2,%3}, [%4];"
                 : "=r"(r[0]), "=r"(r[1]), "=r"(r[2]), "=r"(r[3]) : "r"(addr));
}
__device__ __forceinline__ void ldsm_x4_t(uint32_t* r, uint32_t addr) {
    asm volatile("ldmatrix.sync.aligned.m8n8.x4.trans.shared.b16 {%0,%1,%2,%3}, [%4];"
                 : "=r"(r[0]), "=r"(r[1]), "=r"(r[2]), "=r"(r[3]) : "r"(addr));
}
__device__ __forceinline__ void mma_f16(float* c, const uint32_t* a, const uint32_t* b) {
    asm volatile("mma.sync.aligned.m16n8k16.row.col.f32.f16.f16.f32 "
                 "{%0,%1,%2,%3}, {%4,%5,%6,%7}, {%8,%9}, {%0,%1,%2,%3};"
                 : "+f"(c[0]), "+f"(c[1]), "+f"(c[2]), "+f"(c[3])
                 : "r"(a[0]), "r"(a[1]), "r"(a[2]), "r"(a[3]), "r"(b[0]), "r"(b[1]));
}
__device__ __forceinline__ void cp16(uint32_t dst, const void* src) {
    asm volatile("cp.async.cg.shared.global [%0], [%1], 16;" :: "r"(dst), "l"(src) : "memory");
}
#define CP_COMMIT() asm volatile("cp.async.commit_group;" ::: "memory")

// ---------------- W convert kernel (once, all 4 layers) ----------------
__global__ void __launch_bounds__(256)
wconv_kernel(const float* __restrict__ w0, const float* __restrict__ w1,
             const float* __restrict__ w2, const float* __restrict__ w3,
             __half* __restrict__ wh)
{
    int id = blockIdx.x * 256 + threadIdx.x;
    const float* ws[4] = { w0, w1, w2, w3 };
    wh[id] = __float2half_rn(ws[id >> 16][id & 65535]);
}

// ---------------- Mix: y = A-mix(res), emit fp16 padded-26 ----------------
// sin==26: direct per-row gmem reads; sin==25: slab staging (layer 0 only)
__global__ void __launch_bounds__(256)
mix_kernel(const float* __restrict__ in, const float* __restrict__ Amat,
           __half* __restrict__ yh, int sin)
{
    __shared__ __align__(16) float sbuf[6400];
    __shared__ ull sAp[325];
    const int tid = threadIdx.x;
    const int blk = blockIdx.x;

    for (int i = tid; i < 325; i += 256) {
        int u = i / 13, j = i - u * 13;
        float lo = Amat[(2 * j) * VV + u];
        float hi = (2 * j + 1 < VV) ? Amat[(2 * j + 1) * VV + u] : 0.f;
        sAp[i] = pack2f(lo, hi);
    }

    float xr[VV + 1];
    if (sin == VP2) {
        const float2* src = (const float2*)(in + (size_t)blk * (256 * VP2) + tid * VP2);
#pragma unroll
        for (int j = 0; j < 13; j++) {
            float2 v = src[j];
            xr[2 * j] = v.x; xr[2 * j + 1] = v.y;
        }
        __syncthreads();   // sAp ready
    } else {
        const float4* src = (const float4*)(in + (size_t)blk * (256 * 25));
        float4* dst = (float4*)sbuf;
        for (int i = tid; i < 1600; i += 256) dst[i] = src[i];
        __syncthreads();
        const int rb = tid * 25;
#pragma unroll
        for (int u = 0; u < VV; u++) xr[u] = sbuf[rb + u];
        __syncthreads();   // reads done before sbuf reuse
    }

    ull acc[13];
#pragma unroll
    for (int j = 0; j < 13; j++) acc[j] = 0ULL;
#pragma unroll
    for (int u = 0; u < VV; u++) {
        ull xu2 = pack2(xr[u]);
#pragma unroll
        for (int j = 0; j < 13; j++) acc[j] = ffma2(sAp[u * 13 + j], xu2, acc[j]);
    }

    // convert in registers, store 13 x STS.32 (13 coprime 32 => conflict-free)
    {
        uint32_t* so = (uint32_t*)sbuf + tid * 13;
#pragma unroll
        for (int j = 0; j < 13; j++) {
            __half2 h = __floats2half2_rn(lo32(acc[j]), hi32(acc[j]));
            so[j] = *(uint32_t*)&h;     // j==12 hi == 0 via A pad row
        }
    }
    __syncthreads();

    // emit: 832 x (LDS.128 + STG.128), fully coalesced
    {
        uint4* yh128 = (uint4*)((uint32_t*)yh + (size_t)blk * 3328);
        const uint4* s128 = (const uint4*)sbuf;
        for (int i = tid; i < 832; i += 256) yh128[i] = s128[i];
    }
}

// ---------------- GEMM: out = relu(Wh @ Yh + b + res), fp16 mma.sync ----------------
// grid (13, 2, 64). 3-stage cp.async pipeline, ONE barrier per k-chunk.
// MODE: 0 = res dense25 -> out padded26 (layer 0)
//       1 = padded26 -> padded26         (layers 1,2)
//       2 = padded26 -> out dense25      (layer 3)
#define WS_STRIDE 80
#define YS_STRIDE 272
#define SM_WH 0
#define SM_YH 10240
#define STAGE_BYTES 18944
#define NSTAGE 3
#define SM_TOTAL (NSTAGE * STAGE_BYTES)   // 56,832

template <int MODE>
__global__ void __launch_bounds__(256, 2)
gemm_kernel(const __half* __restrict__ yh, const __half* __restrict__ wh,
            const float* __restrict__ bias, const float* __restrict__ res,
            float* __restrict__ out)
{
    extern __shared__ __align__(16) unsigned char smem[];
    const uint32_t smu = smem_u32(smem);

    const int tid  = threadIdx.x;
    const int lane = tid & 31, wid = tid >> 5;
    const int wm   = wid >> 1, wn = wid & 1;       // 4 (M) x 2 (N)
    const int ct   = blockIdx.x;
    const int mt   = blockIdx.y;
    const int n    = blockIdx.z;
    const int col0 = ct * 128;

    const __half* Wh = wh + (size_t)(mt * 128) * CC;
    const __half* Yh = yh + (size_t)n * CC * TVP + col0;

    auto issue = [&](int kc) {
        const int c0 = kc * 32;
        const uint32_t sbase = smu + (kc % NSTAGE) * STAGE_BYTES;
#pragma unroll
        for (int r = 0; r < 2; r++) {
            const int q = tid + r * 256;
            const int o = q >> 2, p = q & 3;
            const size_t wsrc = (size_t)o * CC + c0 + p * 8;
            cp16(sbase + SM_WH + o * WS_STRIDE + p * 16, Wh + wsrc);
            const int c = q >> 4, jp = q & 15;
            const size_t ysrc = (size_t)(c0 + c) * TVP + jp * 8;
            cp16(sbase + SM_YH + c * YS_STRIDE + jp * 16, Yh + ysrc);
        }
    };

    float acc[2][8][4];
#pragma unroll
    for (int fm = 0; fm < 2; fm++)
#pragma unroll
        for (int nb = 0; nb < 8; nb++)
#pragma unroll
            for (int q = 0; q < 4; q++) acc[fm][nb][q] = 0.f;

    issue(0); CP_COMMIT();
    issue(1); CP_COMMIT();

    for (int kc = 0; kc < 8; kc++) {
        if (kc + 1 < 8) {
            asm volatile("cp.async.wait_group 1;" ::: "memory");
        } else {
            asm volatile("cp.async.wait_group 0;" ::: "memory");
        }
        __syncthreads();

        if (kc + 2 < 8) {
            issue(kc + 2);
            CP_COMMIT();
        }

        const uint32_t st  = smu + (kc % NSTAGE) * STAGE_BYTES;
        const uint32_t swh = st + SM_WH;
        const uint32_t syh = st + SM_YH;

#pragma unroll
        for (int s = 0; s < 2; s++) {
            uint32_t Ah[2][4];
            const uint32_t aoff = (uint32_t)(lane & 15) * WS_STRIDE + s * 32 + (lane >> 4) * 16;
            ldsm_x4(Ah[0], swh + (wm * 32 +  0) * WS_STRIDE + aoff);
            ldsm_x4(Ah[1], swh + (wm * 32 + 16) * WS_STRIDE + aoff);

            const uint32_t boff = (uint32_t)(s * 16 + (lane & 15)) * YS_STRIDE + (lane >> 4) * 16;
#pragma unroll
            for (int nbp = 0; nbp < 4; nbp++) {
                uint32_t Bh[4];
                const uint32_t bcol = (uint32_t)(wn * 64 + nbp * 16) * 2;
                ldsm_x4_t(Bh, syh + boff + bcol);
#pragma unroll
                for (int h = 0; h < 2; h++) {
                    const int nb = nbp * 2 + h;
                    mma_f16(acc[0][nb], Ah[0], &Bh[2 * h]);
                    mma_f16(acc[1][nb], Ah[1], &Bh[2 * h]);
                }
            }
        }
    }

    // ---- epilogue: relu(acc + b[o] + res) ----
    const int g = lane >> 2, tig = lane & 3;

#pragma unroll
    for (int fm = 0; fm < 2; fm++) {
        const int o0 = mt * 128 + wm * 32 + fm * 16 + g;
#pragma unroll
        for (int half = 0; half < 2; half++) {
            const int orow = o0 + half * 8;
            const float bs = bias[orow];
            const size_t rowb = (size_t)n * CC + orow;
#pragma unroll
            for (int nb = 0; nb < 8; nb++) {
                const int j = col0 + wn * 64 + nb * 8 + 2 * tig;
                const float a0 = acc[fm][nb][2 * half];
                const float a1 = acc[fm][nb][2 * half + 1];

                float r0v, r1v;
                if (MODE == 0) {
                    const int t0 = j / VP2, v0 = j - t0 * VP2;
                    const float* rp = res + ((rowb * TT + t0) * VV + v0);
                    r0v = (v0 < VV) ? rp[0] : 0.f;
                    r1v = (v0 + 1 < VV) ? rp[1] : 0.f;
                } else {
                    float2 rr = *(const float2*)(res + rowb * TVP + j);
                    r0v = rr.x; r1v = rr.y;
                }
                const float o0v = fmaxf(a0 + bs + r0v, 0.f);
                const float o1v = fmaxf(a1 + bs + r1v, 0.f);
                if (MODE == 2) {
                    const int t0 = j / VP2, v0 = j - t0 * VP2;
                    float* po = out + ((rowb * TT + t0) * VV + v0);
                    if (v0 < VV) po[0] = o0v;
                    if (v0 + 1 < VV) po[1] = o1v;
                } else {
                    *(float2*)(out + rowb * TVP + j) = make_float2(o0v, o1v);
                }
            }
        }
    }
}

// ---------------- launch ----------------
extern "C" void kernel_launch(void* const* d_in, const int* in_sizes, int n_in,
                              void* d_out, int out_size)
{
    // metadata order: t, x, A, w1, b1, w2, b2, w3, b3, w4, b4
    const float* x  = (const float*)d_in[1];
    const float* A  = (const float*)d_in[2];
    const float* W[4] = { (const float*)d_in[3], (const float*)d_in[5],
                          (const float*)d_in[7], (const float*)d_in[9] };
    const float* B[4] = { (const float*)d_in[4], (const float*)d_in[6],
                          (const float*)d_in[8], (const float*)d_in[10] };
    float* out = (float*)d_out;

    float *r0, *r1;
    __half *yh, *whp;
    cudaGetSymbolAddress((void**)&r0,  g_r0);
    cudaGetSymbolAddress((void**)&r1,  g_r1);
    cudaGetSymbolAddress((void**)&yh,  g_yh);
    cudaGetSymbolAddress((void**)&whp, g_wh);

    cudaFuncSetAttribute(gemm_kernel<0>,
                         cudaFuncAttributeMaxDynamicSharedMemorySize, SM_TOTAL);
    cudaFuncSetAttribute(gemm_kernel<1>,
                         cudaFuncAttributeMaxDynamicSharedMemorySize, SM_TOTAL);
    cudaFuncSetAttribute(gemm_kernel<2>,
                         cudaFuncAttributeMaxDynamicSharedMemorySize, SM_TOTAL);

    wconv_kernel<<<1024, 256>>>(W[0], W[1], W[2], W[3], whp);

    dim3 ggrid(13, 2, NN);

    // layer 0: res = x (dense 25), out = r0 (padded)
    mix_kernel<<<NROWS / 256, 256>>>(x, A, yh, 25);
    gemm_kernel<0><<<ggrid, 256, SM_TOTAL>>>(yh, whp + 0 * CC * CC, B[0], x, r0);
    // layer 1: padded -> padded (r0 -> r1)
    mix_kernel<<<NROWS / 256, 256>>>(r0, A, yh, 26);
    gemm_kernel<1><<<ggrid, 256, SM_TOTAL>>>(yh, whp + 1 * CC * CC, B[1], r0, r1);
    // layer 2: padded -> padded (r1 -> r0)
    mix_kernel<<<NROWS / 256, 256>>>(r1, A, yh, 26);
    gemm_kernel<1><<<ggrid, 256, SM_TOTAL>>>(yh, whp + 2 * CC * CC, B[2], r1, r0);
    // layer 3: padded -> dense out
    mix_kernel<<<NROWS / 256, 256>>>(r0, A, yh, 26);
    gemm_kernel<2><<<ggrid, 256, SM_TOTAL>>>(yh, whp + 3 * CC * CC, B[3], r0, out);
}

// round 16
// speedup vs baseline: 1.3777x; 1.1733x over previous
#include <cuda_runtime.h>
#include <cuda_fp16.h>
#include <cstdint>

#define NN 64
#define CC 256
#define TT 64
#define VV 25
#define VP2 26
#define TVP (TT * VP2)            // 1664 padded cols = 13 x 128
#define NROWS (NN * CC * TT)
#define ELEMS26 (NROWS * VP2)

typedef unsigned long long ull;

// Device scratch (no cudaMalloc allowed)
__device__ float g_r0[ELEMS26];                  // residual ping (padded 26)
__device__ float g_r1[ELEMS26];                  // residual pong (padded 26)
__device__ __half g_yh[ELEMS26];                 // mixed, fp16 (padded 26)
__device__ __half g_wh[4 * CC * CC];             // W fp16 (rounded)

// ---------------- PTX helpers ----------------
__device__ __forceinline__ uint32_t smem_u32(const void* p) {
    uint32_t a;
    asm("{ .reg .u64 t; cvta.to.shared.u64 t, %1; cvt.u32.u64 %0, t; }" : "=r"(a) : "l"(p));
    return a;
}
__device__ __forceinline__ void ldsm_x4(uint32_t* r, uint32_t addr) {
    asm volatile("ldmatrix.sync.aligned.m8n8.x4.shared.b16 {%0,%1,%2,%3}, [%4];"
                 : "=r"(r[0]), "=r"(r[1]), "=r"(r[2]), "=r"(r[3]) : "r"(addr));
}
__device__ __forceinline__ void ldsm_x4_t(uint32_t* r, uint32_t addr) {
    asm volatile("ldmatrix.sync.aligned.m8n8.x4.trans.shared.b16 {%0,%1,%2,%3}, [%4];"
                 : "=r"(r[0]), "=r"(r[1]), "=r"(r[2]), "=r"(r[3]) : "r"(addr));
}
__device__ __forceinline__ void mma_f16(float* c, const uint32_t* a, const uint32_t* b) {
    asm volatile("mma.sync.aligned.m16n8k16.row.col.f32.f16.f16.f32 "
                 "{%0,%1,%2,%3}, {%4,%5,%6,%7}, {%8,%9}, {%0,%1,%2,%3};"
                 : "+f"(c[0]), "+f"(c[1]), "+f"(c[2]), "+f"(c[3])
                 : "r"(a[0]), "r"(a[1]), "r"(a[2]), "r"(a[3]), "r"(b[0]), "r"(b[1]));
}
__device__ __forceinline__ void cp16(uint32_t dst, const void* src) {
    asm volatile("cp.async.cg.shared.global [%0], [%1], 16;" :: "r"(dst), "l"(src) : "memory");
}
#define CP_COMMIT() asm volatile("cp.async.commit_group;" ::: "memory")

// ---------------- W convert kernel (once, all 4 layers) ----------------
__global__ void __launch_bounds__(256)
wconv_kernel(const float* __restrict__ w0, const float* __restrict__ w1,
             const float* __restrict__ w2, const float* __restrict__ w3,
             __half* __restrict__ wh)
{
    int id = blockIdx.x * 256 + threadIdx.x;
    const float* ws[4] = { w0, w1, w2, w3 };
    wh[id] = __float2half_rn(ws[id >> 16][id & 65535]);
}

// ---------------- Mix via tensor cores: y[row,v] = sum_u x[row,u] A[v,u] ----------------
// 256 rows/CTA, 8 warps x (2 m16 tiles). K=26->32, N=26->32 padded.
// Dynamic smem layout:
//   [0,      25600)  slab (layer-0 fp32 staging) / out staging (3328 u32)
//   [25600,  46080)  X fp16 [256 rows][40 halves] (80B stride)
//   [46080,  48640)  As fp16 [32 u][40 halves]: As[u][v] = A[v][u], zero-padded
#define MIX_XOFF 25600
#define MIX_AOFF 46080
#define MIX_SMEM 48640
#define XS 40

__global__ void __launch_bounds__(256)
mix_kernel(const float* __restrict__ in, const float* __restrict__ Amat,
           __half* __restrict__ yh, int sin)
{
    extern __shared__ __align__(16) unsigned char dsm[];
    float*  slab = (float*)dsm;
    __half* Xs   = (__half*)(dsm + MIX_XOFF);
    __half* As   = (__half*)(dsm + MIX_AOFF);

    const int tid  = threadIdx.x;
    const int lane = tid & 31, wid = tid >> 5;
    const int blk  = blockIdx.x;

    // stage As[u][v] = A[v][u], zero-padded to 32x32
    for (int i = tid; i < 1024; i += 256) {
        int u = i >> 5, v = i & 31;
        float a = (u < VV && v < VV) ? Amat[v * VV + u] : 0.f;
        As[u * XS + v] = __float2half_rn(a);
    }

    // stage X row tid as fp16 (cols 26..31 zeroed)
    {
        __half2* xrow = (__half2*)(Xs + tid * XS);
        if (sin == VP2) {
            const float2* src = (const float2*)(in + (size_t)blk * (256 * VP2) + tid * VP2);
#pragma unroll
            for (int j = 0; j < 13; j++) {
                float2 v = src[j];
                xrow[j] = __floats2half2_rn(v.x, v.y);
            }
        } else {
            const float4* src = (const float4*)(in + (size_t)blk * (256 * 25));
            float4* dst = (float4*)slab;
            for (int i = tid; i < 1600; i += 256) dst[i] = src[i];
            __syncthreads();
            const float* xr = slab + tid * 25;
#pragma unroll
            for (int j = 0; j < 12; j++)
                xrow[j] = __floats2half2_rn(xr[2 * j], xr[2 * j + 1]);
            xrow[12] = __floats2half2_rn(xr[24], 0.f);
        }
        xrow[13] = __half2(); xrow[14] = __half2(); xrow[15] = __half2();
    }
    __syncthreads();

    // MMA: warp owns rows wid*32 .. wid*32+31 (two m16 tiles)
    const uint32_t xsu = smem_u32(Xs);
    const uint32_t asu = smem_u32(As);

    float acc[2][4][4];
#pragma unroll
    for (int m = 0; m < 2; m++)
#pragma unroll
        for (int nb = 0; nb < 4; nb++)
#pragma unroll
            for (int q = 0; q < 4; q++) acc[m][nb][q] = 0.f;

#pragma unroll
    for (int s = 0; s < 2; s++) {
        uint32_t Af[2][4];
        const uint32_t aoff = (uint32_t)(lane & 15) * 80 + s * 32 + (lane >> 4) * 16;
        ldsm_x4(Af[0], xsu + (wid * 32 +  0) * 80 + aoff);
        ldsm_x4(Af[1], xsu + (wid * 32 + 16) * 80 + aoff);

        const uint32_t boff = (uint32_t)(s * 16 + (lane & 15)) * 80 + (lane >> 4) * 16;
#pragma unroll
        for (int nbp = 0; nbp < 2; nbp++) {
            uint32_t Bf[4];
            ldsm_x4_t(Bf, asu + boff + nbp * 32);
#pragma unroll
            for (int h = 0; h < 2; h++) {
                const int nb = nbp * 2 + h;
                mma_f16(acc[0][nb], Af[0], &Bf[2 * h]);
                mma_f16(acc[1][nb], Af[1], &Bf[2 * h]);
            }
        }
    }

    // epilogue: scatter half2 pairs to out staging (u32 index j = nb*4+tig < 13)
    {
        uint32_t* so = (uint32_t*)slab;
        const int g = lane >> 2, tig = lane & 3;
#pragma unroll
        for (int m = 0; m < 2; m++) {
            const int row = wid * 32 + m * 16 + g;
#pragma unroll
            for (int nb = 0; nb < 4; nb++) {
                const int j = nb * 4 + tig;
                if (j < 13) {
                    __half2 h0 = __floats2half2_rn(acc[m][nb][0], acc[m][nb][1]);
                    __half2 h1 = __floats2half2_rn(acc[m][nb][2], acc[m][nb][3]);
                    so[row * 13 + j]       = *(uint32_t*)&h0;
                    so[(row + 8) * 13 + j] = *(uint32_t*)&h1;
                }
            }
        }
    }
    __syncthreads();

    // coalesced copy-out: 832 x uint4
    {
        uint4* yh128 = (uint4*)((uint32_t*)yh + (size_t)blk * 3328);
        const uint4* s128 = (const uint4*)slab;
        for (int i = tid; i < 832; i += 256) yh128[i] = s128[i];
    }
}

// ---------------- GEMM: out = relu(Wh @ Yh + b + res), fp16 mma.sync ----------------
// grid (13, 2, 64). 3-stage cp.async pipeline, ONE barrier per k-chunk.
// MODE: 0 = res dense25 -> out padded26 (layer 0)
//       1 = padded26 -> padded26         (layers 1,2)
//       2 = padded26 -> out dense25      (layer 3)
#define WS_STRIDE 80
#define YS_STRIDE 272
#define SM_WH 0
#define SM_YH 10240
#define STAGE_BYTES 18944
#define NSTAGE 3
#define SM_TOTAL (NSTAGE * STAGE_BYTES)   // 56,832

template <int MODE>
__global__ void __launch_bounds__(256, 2)
gemm_kernel(const __half* __restrict__ yh, const __half* __restrict__ wh,
            const float* __restrict__ bias, const float* __restrict__ res,
            float* __restrict__ out)
{
    extern __shared__ __align__(16) unsigned char smem[];
    const uint32_t smu = smem_u32(smem);

    const int tid  = threadIdx.x;
    const int lane = tid & 31, wid = tid >> 5;
    const int wm   = wid >> 1, wn = wid & 1;       // 4 (M) x 2 (N)
    const int ct   = blockIdx.x;
    const int mt   = blockIdx.y;
    const int n    = blockIdx.z;
    const int col0 = ct * 128;

    const __half* Wh = wh + (size_t)(mt * 128) * CC;
    const __half* Yh = yh + (size_t)n * CC * TVP + col0;

    auto issue = [&](int kc) {
        const int c0 = kc * 32;
        const uint32_t sbase = smu + (kc % NSTAGE) * STAGE_BYTES;
#pragma unroll
        for (int r = 0; r < 2; r++) {
            const int q = tid + r * 256;
            const int o = q >> 2, p = q & 3;
            const size_t wsrc = (size_t)o * CC + c0 + p * 8;
            cp16(sbase + SM_WH + o * WS_STRIDE + p * 16, Wh + wsrc);
            const int c = q >> 4, jp = q & 15;
            const size_t ysrc = (size_t)(c0 + c) * TVP + jp * 8;
            cp16(sbase + SM_YH + c * YS_STRIDE + jp * 16, Yh + ysrc);
        }
    };

    float acc[2][8][4];
#pragma unroll
    for (int fm = 0; fm < 2; fm++)
#pragma unroll
        for (int nb = 0; nb < 8; nb++)
#pragma unroll
            for (int q = 0; q < 4; q++) acc[fm][nb][q] = 0.f;

    issue(0); CP_COMMIT();
    issue(1); CP_COMMIT();

    for (int kc = 0; kc < 8; kc++) {
        if (kc + 1 < 8) {
            asm volatile("cp.async.wait_group 1;" ::: "memory");
        } else {
            asm volatile("cp.async.wait_group 0;" ::: "memory");
        }
        __syncthreads();

        if (kc + 2 < 8) {
            issue(kc + 2);
            CP_COMMIT();
        }

        const uint32_t st  = smu + (kc % NSTAGE) * STAGE_BYTES;
        const uint32_t swh = st + SM_WH;
        const uint32_t syh = st + SM_YH;

#pragma unroll
        for (int s = 0; s < 2; s++) {
            uint32_t Ah[2][4];
            const uint32_t aoff = (uint32_t)(lane & 15) * WS_STRIDE + s * 32 + (lane >> 4) * 16;
            ldsm_x4(Ah[0], swh + (wm * 32 +  0) * WS_STRIDE + aoff);
            ldsm_x4(Ah[1], swh + (wm * 32 + 16) * WS_STRIDE + aoff);

            const uint32_t boff = (uint32_t)(s * 16 + (lane & 15)) * YS_STRIDE + (lane >> 4) * 16;
#pragma unroll
            for (int nbp = 0; nbp < 4; nbp++) {
                uint32_t Bh[4];
                const uint32_t bcol = (uint32_t)(wn * 64 + nbp * 16) * 2;
                ldsm_x4_t(Bh, syh + boff + bcol);
#pragma unroll
                for (int h = 0; h < 2; h++) {
                    const int nb = nbp * 2 + h;
                    mma_f16(acc[0][nb], Ah[0], &Bh[2 * h]);
                    mma_f16(acc[1][nb], Ah[1], &Bh[2 * h]);
                }
            }
        }
    }

    // ---- epilogue: relu(acc + b[o] + res) ----
    const int g = lane >> 2, tig = lane & 3;

#pragma unroll
    for (int fm = 0; fm < 2; fm++) {
        const int o0 = mt * 128 + wm * 32 + fm * 16 + g;
#pragma unroll
        for (int half = 0; half < 2; half++) {
            const int orow = o0 + half * 8;
            const float bs = bias[orow];
            const size_t rowb = (size_t)n * CC + orow;
#pragma unroll
            for (int nb = 0; nb < 8; nb++) {
                const int j = col0 + wn * 64 + nb * 8 + 2 * tig;
                const float a0 = acc[fm][nb][2 * half];
                const float a1 = acc[fm][nb][2 * half + 1];

                float r0v, r1v;
                if (MODE == 0) {
                    const int t0 = j / VP2, v0 = j - t0 * VP2;
                    const float* rp = res + ((rowb * TT + t0) * VV + v0);
                    r0v = (v0 < VV) ? rp[0] : 0.f;
                    r1v = (v0 + 1 < VV) ? rp[1] : 0.f;
                } else {
                    float2 rr = *(const float2*)(res + rowb * TVP + j);
                    r0v = rr.x; r1v = rr.y;
                }
                const float o0v = fmaxf(a0 + bs + r0v, 0.f);
                const float o1v = fmaxf(a1 + bs + r1v, 0.f);
                if (MODE == 2) {
                    const int t0 = j / VP2, v0 = j - t0 * VP2;
                    float* po = out + ((rowb * TT + t0) * VV + v0);
                    if (v0 < VV) po[0] = o0v;
                    if (v0 + 1 < VV) po[1] = o1v;
                } else {
                    *(float2*)(out + rowb * TVP + j) = make_float2(o0v, o1v);
                }
            }
        }
    }
}

// ---------------- launch ----------------
extern "C" void kernel_launch(void* const* d_in, const int* in_sizes, int n_in,
                              void* d_out, int out_size)
{
    // metadata order: t, x, A, w1, b1, w2, b2, w3, b3, w4, b4
    const float* x  = (const float*)d_in[1];
    const float* A  = (const float*)d_in[2];
    const float* W[4] = { (const float*)d_in[3], (const float*)d_in[5],
                          (const float*)d_in[7], (const float*)d_in[9] };
    const float* B[4] = { (const float*)d_in[4], (const float*)d_in[6],
                          (const float*)d_in[8], (const float*)d_in[10] };
    float* out = (float*)d_out;

    float *r0, *r1;
    __half *yh, *whp;
    cudaGetSymbolAddress((void**)&r0,  g_r0);
    cudaGetSymbolAddress((void**)&r1,  g_r1);
    cudaGetSymbolAddress((void**)&yh,  g_yh);
    cudaGetSymbolAddress((void**)&whp, g_wh);

    cudaFuncSetAttribute(gemm_kernel<0>,
                         cudaFuncAttributeMaxDynamicSharedMemorySize, SM_TOTAL);
    cudaFuncSetAttribute(gemm_kernel<1>,
                         cudaFuncAttributeMaxDynamicSharedMemorySize, SM_TOTAL);
    cudaFuncSetAttribute(gemm_kernel<2>,
                         cudaFuncAttributeMaxDynamicSharedMemorySize, SM_TOTAL);
    cudaFuncSetAttribute(mix_kernel,
                         cudaFuncAttributeMaxDynamicSharedMemorySize, MIX_SMEM);

    wconv_kernel<<<1024, 256>>>(W[0], W[1], W[2], W[3], whp);

    dim3 ggrid(13, 2, NN);

    // layer 0: res = x (dense 25), out = r0 (padded)
    mix_kernel<<<NROWS / 256, 256, MIX_SMEM>>>(x, A, yh, 25);
    gemm_kernel<0><<<ggrid, 256, SM_TOTAL>>>(yh, whp + 0 * CC * CC, B[0], x, r0);
    // layer 1: padded -> padded (r0 -> r1)
    mix_kernel<<<NROWS / 256, 256, MIX_SMEM>>>(r0, A, yh, 26);
    gemm_kernel<1><<<ggrid, 256, SM_TOTAL>>>(yh, whp + 1 * CC * CC, B[1], r0, r1);
    // layer 2: padded -> padded (r1 -> r0)
    mix_kernel<<<NROWS / 256, 256, MIX_SMEM>>>(r1, A, yh, 26);
    gemm_kernel<1><<<ggrid, 256, SM_TOTAL>>>(yh, whp + 2 * CC * CC, B[2], r1, r0);
    // layer 3: padded -> dense out
    mix_kernel<<<NROWS / 256, 256, MIX_SMEM>>>(r0, A, yh, 26);
    gemm_kernel<2><<<ggrid, 256, SM_TOTAL>>>(yh, whp + 3 * CC * CC, B[3], r0, out);
}